// round 1
// baseline (speedup 1.0000x reference)
#include <cuda_runtime.h>
#include <cuda_bf16.h>
#include <math.h>

// Problem constants (fixed shapes per reference)
#define NN   50000
#define EE   800000
#define IN_D 256
#define HC   256      // H*C
#define HH   4
#define CC   64
#define LAT  32

// ---------------- device scratch (globals: no allocation allowed) ----------
__device__ float g_xl[NN * HC];      // 51.2 MB
__device__ float g_xr[NN * HC];      // 51.2 MB
__device__ float g_h [NN * CC];      // 12.8 MB
__device__ float g_loop[NN * 3];
__device__ int   g_deg [NN];
__device__ int   g_off [NN + 1];
__device__ int   g_fill[NN];
__device__ int   g_csr [EE];

// ---------------- graph preprocessing ---------------------------------------
__global__ void init_kernel() {
    int i = blockIdx.x * blockDim.x + threadIdx.x;
    if (i < NN) { g_deg[i] = 0; g_fill[i] = 0; }
    if (i < NN * 3) g_loop[i] = 0.f;
}

__global__ void edge_deg_kernel(const int* __restrict__ dst,
                                const float* __restrict__ edge_attr) {
    int e = blockIdx.x * blockDim.x + threadIdx.x;
    if (e >= EE) return;
    int d = dst[e];
    atomicAdd(&g_deg[d], 1);
    atomicAdd(&g_loop[d * 3 + 0], edge_attr[e * 3 + 0]);
    atomicAdd(&g_loop[d * 3 + 1], edge_attr[e * 3 + 1]);
    atomicAdd(&g_loop[d * 3 + 2], edge_attr[e * 3 + 2]);
}

__global__ void loop_fin_kernel() {
    int n = blockIdx.x * blockDim.x + threadIdx.x;
    if (n >= NN) return;
    float inv = 1.f / fmaxf((float)g_deg[n], 1.f);
    g_loop[n * 3 + 0] *= inv;
    g_loop[n * 3 + 1] *= inv;
    g_loop[n * 3 + 2] *= inv;
}

// single-block exclusive scan of g_deg -> g_off
__global__ void scan_kernel() {
    __shared__ int ssum[1024];
    int t = threadIdx.x;
    const int Mc = (NN + 1023) / 1024;   // 49
    int start = t * Mc;
    int end   = min(start + Mc, NN);
    int s = 0;
    for (int i = start; i < end; i++) s += g_deg[i];
    ssum[t] = s;
    __syncthreads();
    for (int ofs = 1; ofs < 1024; ofs <<= 1) {
        int v = (t >= ofs) ? ssum[t - ofs] : 0;
        __syncthreads();
        ssum[t] += v;
        __syncthreads();
    }
    int run = ssum[t] - s;    // exclusive
    for (int i = start; i < end; i++) { g_off[i] = run; run += g_deg[i]; }
    if (t == 1023) g_off[NN] = ssum[1023];
}

__global__ void csr_fill_kernel(const int* __restrict__ dst) {
    int e = blockIdx.x * blockDim.x + threadIdx.x;
    if (e >= EE) return;
    int d = dst[e];
    int pos = g_off[d] + atomicAdd(&g_fill[d], 1);
    g_csr[pos] = e;
}

// ---------------- SGEMM: C[M,NC] = A[M,K] @ B[K,NC] + bias ------------------
// 64x64 block tile, BK=16, 256 threads, 4x4 per-thread micro-tile.
__global__ __launch_bounds__(256)
void gemm_bias_kernel(const float* __restrict__ A, const float* __restrict__ B,
                      const float* __restrict__ bias, float* __restrict__ C,
                      int M, int K, int NC) {
    __shared__ float As[16][65];
    __shared__ float Bs[16][64];
    int bm = blockIdx.x * 64;
    int bn = blockIdx.y * 64;
    int tid = threadIdx.x;
    int tx = tid & 15, ty = tid >> 4;
    float acc[4][4] = {};
    for (int k0 = 0; k0 < K; k0 += 16) {
        int kk = tid & 15;
        #pragma unroll
        for (int m = tid >> 4; m < 64; m += 16) {
            int gr = bm + m;
            As[kk][m] = (gr < M) ? A[(size_t)gr * K + k0 + kk] : 0.f;
        }
        int nn = tid & 63;
        #pragma unroll
        for (int kb = tid >> 6; kb < 16; kb += 4) {
            Bs[kb][nn] = B[(size_t)(k0 + kb) * NC + bn + nn];
        }
        __syncthreads();
        #pragma unroll
        for (int k2 = 0; k2 < 16; k2++) {
            float a[4], b[4];
            #pragma unroll
            for (int i = 0; i < 4; i++) a[i] = As[k2][ty * 4 + i];
            #pragma unroll
            for (int j = 0; j < 4; j++) b[j] = Bs[k2][tx * 4 + j];
            #pragma unroll
            for (int i = 0; i < 4; i++)
                #pragma unroll
                for (int j = 0; j < 4; j++)
                    acc[i][j] += a[i] * b[j];
        }
        __syncthreads();
    }
    #pragma unroll
    for (int i = 0; i < 4; i++) {
        int gr = bm + ty * 4 + i;
        if (gr >= M) continue;
        #pragma unroll
        for (int j = 0; j < 4; j++) {
            int gc = bn + tx * 4 + j;
            C[(size_t)gr * NC + gc] = acc[i][j] + bias[gc];
        }
    }
}

// ---------------- GATv2 aggregation: one warp per dst node ------------------
__global__ __launch_bounds__(256)
void gat_agg_kernel(const float* __restrict__ xl, const float* __restrict__ xr,
                    const float* __restrict__ edge_attr,
                    const int* __restrict__ srcarr,
                    const float* __restrict__ We, const float* __restrict__ att,
                    const float* __restrict__ bias, float* __restrict__ out) {
    int warp = (blockIdx.x * blockDim.x + threadIdx.x) >> 5;
    if (warp >= NN) return;
    int lane  = threadIdx.x & 31;
    int node  = warp;
    int jbase = lane * 8;

    float we0[8], we1[8], we2[8], attv[8], xrv[8];
    #pragma unroll
    for (int i = 0; i < 8; i++) {
        int j = jbase + i;
        we0[i]  = We[j];
        we1[i]  = We[256 + j];
        we2[i]  = We[512 + j];
        attv[i] = att[j];
        xrv[i]  = xr[(size_t)node * HC + j];
    }

    float mx = -1e30f, denom = 0.f;
    float acc[8] = {};
    int e0 = g_off[node], e1 = g_off[node + 1];

    for (int t = e0; t <= e1; t++) {      // last iteration = self loop
        int s; float ea0, ea1, ea2;
        if (t < e1) {
            int e = g_csr[t];
            s = srcarr[e];
            ea0 = edge_attr[e * 3 + 0];
            ea1 = edge_attr[e * 3 + 1];
            ea2 = edge_attr[e * 3 + 2];
        } else {
            s = node;
            ea0 = g_loop[node * 3 + 0];
            ea1 = g_loop[node * 3 + 1];
            ea2 = g_loop[node * 3 + 2];
        }
        float xlv[8];
        const float4* p = (const float4*)(xl + (size_t)s * HC + jbase);
        float4 v0 = p[0], v1 = p[1];
        xlv[0] = v0.x; xlv[1] = v0.y; xlv[2] = v0.z; xlv[3] = v0.w;
        xlv[4] = v1.x; xlv[5] = v1.y; xlv[6] = v1.z; xlv[7] = v1.w;

        float part = 0.f;
        #pragma unroll
        for (int i = 0; i < 8; i++) {
            float m = xlv[i] + xrv[i] + ea0 * we0[i] + ea1 * we1[i] + ea2 * we2[i];
            m = (m > 0.f) ? m : 0.2f * m;
            part += m * attv[i];
        }
        // reduce over the 8 lanes of this head
        part += __shfl_xor_sync(0xffffffff, part, 1);
        part += __shfl_xor_sync(0xffffffff, part, 2);
        part += __shfl_xor_sync(0xffffffff, part, 4);
        float alpha = part;

        // online softmax (== segment-max softmax)
        float nm = fmaxf(mx, alpha);
        float sc = __expf(mx - nm);
        float pw = __expf(alpha - nm);
        denom = denom * sc + pw;
        #pragma unroll
        for (int i = 0; i < 8; i++) acc[i] = acc[i] * sc + pw * xlv[i];
        mx = nm;
    }

    float inv = 1.f / denom;
    #pragma unroll
    for (int i = 0; i < 8; i++) {
        float r = acc[i] * inv;
        // mean over the 4 heads: lanes l, l^8, l^16, l^24
        r += __shfl_xor_sync(0xffffffff, r, 8);
        r += __shfl_xor_sync(0xffffffff, r, 16);
        acc[i] = r * 0.25f;
    }
    if (lane < 8) {
        #pragma unroll
        for (int i = 0; i < 8; i++) {
            int c = jbase + i;   // lane<8 -> c in [0,64)
            out[(size_t)node * CC + c] = fmaxf(acc[i] + bias[c], 0.f);
        }
    }
}

// ---------------- final projection: out = h @ Wmu + bmu ---------------------
__global__ __launch_bounds__(256)
void mu_kernel(const float* __restrict__ h, const float* __restrict__ Wmu,
               const float* __restrict__ bmu, float* __restrict__ out) {
    __shared__ float sW[CC * LAT];
    __shared__ float sb[LAT];
    int tid = threadIdx.x;
    for (int i = tid; i < CC * LAT; i += 256) sW[i] = Wmu[i];
    if (tid < LAT) sb[tid] = bmu[tid];
    __syncthreads();
    int warp = tid >> 5, lane = tid & 31;
    int node = blockIdx.x * 8 + warp;
    if (node >= NN) return;
    const float* hr = h + (size_t)node * CC;
    float sum = sb[lane];
    #pragma unroll
    for (int c = 0; c < CC; c++)
        sum += hr[c] * sW[c * LAT + lane];
    out[(size_t)node * LAT + lane] = sum;
}

// ---------------- host launcher ---------------------------------------------
extern "C" void kernel_launch(void* const* d_in, const int* in_sizes, int n_in,
                              void* d_out, int out_size) {
    const float* x   = (const float*)d_in[0];
    const int*   ei  = (const int*)  d_in[1];
    const float* ea  = (const float*)d_in[2];
    const float* Wl0 = (const float*)d_in[3];
    const float* bl0 = (const float*)d_in[4];
    const float* Wr0 = (const float*)d_in[5];
    const float* br0 = (const float*)d_in[6];
    const float* We0 = (const float*)d_in[7];
    const float* at0 = (const float*)d_in[8];
    const float* bi0 = (const float*)d_in[9];
    const float* Wl1 = (const float*)d_in[10];
    const float* bl1 = (const float*)d_in[11];
    const float* Wr1 = (const float*)d_in[12];
    const float* br1 = (const float*)d_in[13];
    const float* We1 = (const float*)d_in[14];
    const float* at1 = (const float*)d_in[15];
    const float* bi1 = (const float*)d_in[16];
    const float* Wmu = (const float*)d_in[17];
    const float* bmu = (const float*)d_in[18];
    float* out = (float*)d_out;

    const int* src = ei;        // row 0
    const int* dst = ei + EE;   // row 1

    float* xl; cudaGetSymbolAddress((void**)&xl, g_xl);
    float* xr; cudaGetSymbolAddress((void**)&xr, g_xr);
    float* h ; cudaGetSymbolAddress((void**)&h , g_h );

    // ---- graph preprocessing (layer independent) ----
    init_kernel<<<(NN * 3 + 255) / 256, 256>>>();
    edge_deg_kernel<<<(EE + 255) / 256, 256>>>(dst, ea);
    loop_fin_kernel<<<(NN + 255) / 256, 256>>>();
    scan_kernel<<<1, 1024>>>();
    csr_fill_kernel<<<(EE + 255) / 256, 256>>>(dst);

    dim3 gemm_grid0((NN + 63) / 64, HC / 64);
    dim3 agg_grid((NN + 7) / 8);

    // ---- layer 0 ----
    gemm_bias_kernel<<<gemm_grid0, 256>>>(x, Wl0, bl0, xl, NN, IN_D, HC);
    gemm_bias_kernel<<<gemm_grid0, 256>>>(x, Wr0, br0, xr, NN, IN_D, HC);
    gat_agg_kernel<<<agg_grid, 256>>>(xl, xr, ea, src, We0, at0, bi0, h);

    // ---- layer 1 ----
    gemm_bias_kernel<<<gemm_grid0, 256>>>(h, Wl1, bl1, xl, NN, CC, HC);
    gemm_bias_kernel<<<gemm_grid0, 256>>>(h, Wr1, br1, xr, NN, CC, HC);
    gat_agg_kernel<<<agg_grid, 256>>>(xl, xr, ea, src, We1, at1, bi1, h);

    // ---- projection ----
    mu_kernel<<<(NN + 7) / 8, 256>>>(h, Wmu, bmu, out);
}